// round 1
// baseline (speedup 1.0000x reference)
#include <cuda_runtime.h>

// MPNN: B=4096 graphs, N=64 nodes, D=128, L=3 layers.
// One CTA per graph. All per-graph state (h, z, adj) lives in shared memory;
// W[l] is staged per layer. h is kept TRANSPOSED (ht[d][m]) so both GEMMs are
// K-minor on both operands and no transposes are ever needed:
//   GEMM1: z_t[k][m]  = relu( sum_d W[k][d] * ht[d][m] + b[k] )
//   GEMM2: ht'[dd][m] = z_t[dd][m] + sum_n z_t[dd][n] * adj[m][n]
// Pool:   out[g][d]   = sum_m ht[d][m]

#define SW_STRIDE 132   // W rows padded (breaks 4-row bank aliasing -> 2-way)
#define ZT_STRIDE 68    // z_t rows padded (same)

__global__ __launch_bounds__(256, 1)
void mpnn_kernel(const int*   __restrict__ fps,
                 const float* __restrict__ adj,
                 const float* __restrict__ emb,
                 const float* __restrict__ W,
                 const float* __restrict__ bias,
                 float*       __restrict__ out)
{
    const int g   = blockIdx.x;
    const int tid = threadIdx.x;
    const int tx  = tid & 7;     // m-tile index (8 tiles of 8 cols)
    const int ty  = tid >> 3;    // k/dd-tile index (32 tiles of 4 rows)
    const int k0  = ty << 2;
    const int m0  = tx << 3;

    extern __shared__ float sm[];
    float* sW   = sm;                         // [128][132]
    float* sht  = sW  + 128 * SW_STRIDE;      // [128][64]   h transposed
    float* szt  = sht + 128 * 64;             // [128][68]   z transposed
    float* sadj = szt + 128 * ZT_STRIDE;      // [64][64]    slot-swizzled

    // ---- load adjacency with XOR slot swizzle (16B slots) ----
    // row m, float4-slot s stored at slot s ^ ((m>>3)&7) -> conflict-free
    // GEMM2 B-loads (each thread owns rows m0..m0+7, key == tx).
    {
        const float4* ag = reinterpret_cast<const float4*>(adj) + (size_t)g * 1024;
        #pragma unroll
        for (int i = 0; i < 4; i++) {
            int idx = tid + (i << 8);       // 0..1023
            int m   = idx >> 4;
            int s   = idx & 15;
            int s2  = s ^ ((m >> 3) & 7);
            float4 v = ag[idx];
            *reinterpret_cast<float4*>(sadj + m * 64 + (s2 << 2)) = v;
        }
    }

    // ---- gather embeddings -> ht[d][m] (transposed) ----
    {
        int m  = tid & 63;
        int d4 = tid >> 6;                  // 0..3
        int fp = fps[(g << 6) + m];
        const float4* erow = reinterpret_cast<const float4*>(emb) + ((size_t)fp << 5);
        #pragma unroll
        for (int j = 0; j < 8; j++) {
            int c4 = d4 + (j << 2);         // float4 column 0..31
            float4 v = erow[c4];
            int db = c4 << 2;
            sht[(db + 0) * 64 + m] = v.x;   // m consecutive across lanes:
            sht[(db + 1) * 64 + m] = v.y;   // conflict-free scalar stores
            sht[(db + 2) * 64 + m] = v.z;
            sht[(db + 3) * 64 + m] = v.w;
        }
    }
    __syncthreads();

    for (int l = 0; l < 3; l++) {
        // ---- stage W[l] (natural [k][d] layout, padded rows) ----
        {
            const float4* wg = reinterpret_cast<const float4*>(W) + (size_t)l * 4096;
            #pragma unroll
            for (int i = 0; i < 16; i++) {
                int idx = tid + (i << 8);   // 0..4095
                int k   = idx >> 5;
                int d4  = idx & 31;
                float4 v = wg[idx];
                *reinterpret_cast<float4*>(sW + k * SW_STRIDE + (d4 << 2)) = v;
            }
        }
        __syncthreads();

        // ---- GEMM1: z_t = relu(W @ ht + b), 128x64 output, K=128 ----
        float zr[4][8];
        #pragma unroll
        for (int r = 0; r < 4; r++)
            #pragma unroll
            for (int c = 0; c < 8; c++) zr[r][c] = 0.0f;

        for (int d = 0; d < 128; d += 4) {
            float ar[4][4];
            #pragma unroll
            for (int r = 0; r < 4; r++) {
                float4 t = *reinterpret_cast<const float4*>(sW + (k0 + r) * SW_STRIDE + d);
                ar[r][0] = t.x; ar[r][1] = t.y; ar[r][2] = t.z; ar[r][3] = t.w;
            }
            #pragma unroll
            for (int dd = 0; dd < 4; dd++) {
                const float* hrow = sht + (d + dd) * 64 + m0;
                float4 b0 = *reinterpret_cast<const float4*>(hrow);
                float4 b1 = *reinterpret_cast<const float4*>(hrow + 4);
                float bv[8] = {b0.x, b0.y, b0.z, b0.w, b1.x, b1.y, b1.z, b1.w};
                #pragma unroll
                for (int r = 0; r < 4; r++)
                    #pragma unroll
                    for (int c = 0; c < 8; c++)
                        zr[r][c] = fmaf(ar[r][dd], bv[c], zr[r][c]);
            }
        }

        // bias + relu; keep z in registers AND publish to smem for GEMM2
        #pragma unroll
        for (int r = 0; r < 4; r++) {
            float bb = __ldg(bias + l * 128 + k0 + r);
            #pragma unroll
            for (int c = 0; c < 8; c++) {
                float v = zr[r][c] + bb;
                zr[r][c] = v > 0.0f ? v : 0.0f;
            }
            float* zrow = szt + (k0 + r) * ZT_STRIDE + m0;
            *reinterpret_cast<float4*>(zrow)     = make_float4(zr[r][0], zr[r][1], zr[r][2], zr[r][3]);
            *reinterpret_cast<float4*>(zrow + 4) = make_float4(zr[r][4], zr[r][5], zr[r][6], zr[r][7]);
        }
        __syncthreads();

        // ---- GEMM2 (NT): acc[dd][m] = sum_n z_t[dd][n] * adj[m][n], K=64 ----
        float acc[4][8];
        #pragma unroll
        for (int r = 0; r < 4; r++)
            #pragma unroll
            for (int c = 0; c < 8; c++) acc[r][c] = 0.0f;

        for (int n = 0; n < 64; n += 4) {
            int slot = n >> 2;
            float4 a4[4];
            #pragma unroll
            for (int r = 0; r < 4; r++)
                a4[r] = *reinterpret_cast<const float4*>(szt + (k0 + r) * ZT_STRIDE + n);
            #pragma unroll
            for (int c = 0; c < 8; c++) {
                // de-swizzle: key for row (m0+c) is tx
                float4 b = *reinterpret_cast<const float4*>(
                    sadj + (m0 + c) * 64 + (((slot ^ tx) & 15) << 2));
                #pragma unroll
                for (int r = 0; r < 4; r++) {
                    acc[r][c] = fmaf(a4[r].x, b.x, acc[r][c]);
                    acc[r][c] = fmaf(a4[r].y, b.y, acc[r][c]);
                    acc[r][c] = fmaf(a4[r].z, b.z, acc[r][c]);
                    acc[r][c] = fmaf(a4[r].w, b.w, acc[r][c]);
                }
            }
        }

        // h' = z + adj@z  -> write straight into ht (GEMM2 never reads sht,
        // GEMM1 readers were fenced by the barrier above)
        #pragma unroll
        for (int r = 0; r < 4; r++) {
            float* hrow = sht + (k0 + r) * 64 + m0;
            *reinterpret_cast<float4*>(hrow) = make_float4(
                zr[r][0] + acc[r][0], zr[r][1] + acc[r][1],
                zr[r][2] + acc[r][2], zr[r][3] + acc[r][3]);
            *reinterpret_cast<float4*>(hrow + 4) = make_float4(
                zr[r][4] + acc[r][4], zr[r][5] + acc[r][5],
                zr[r][6] + acc[r][6], zr[r][7] + acc[r][7]);
        }
        __syncthreads();
    }

    // ---- sum pooling: out[g][d] = sum_m ht[d][m] ----
    if (tid < 128) {
        const float4* row = reinterpret_cast<const float4*>(sht + tid * 64);
        float4 s = row[0];
        #pragma unroll
        for (int i = 1; i < 16; i++) {
            float4 v = row[i];
            s.x += v.x; s.y += v.y; s.z += v.z; s.w += v.w;
        }
        out[(g << 7) + tid] = (s.x + s.y) + (s.z + s.w);
    }
}

extern "C" void kernel_launch(void* const* d_in, const int* in_sizes, int n_in,
                              void* d_out, int out_size)
{
    (void)in_sizes; (void)n_in; (void)out_size;
    const int*   fps = (const int*)  d_in[0];
    const float* adj = (const float*)d_in[1];
    const float* emb = (const float*)d_in[2];
    const float* W   = (const float*)d_in[3];
    const float* b   = (const float*)d_in[4];
    float*       out = (float*)d_out;

    const size_t smem = (size_t)(128 * SW_STRIDE + 128 * 64 + 128 * ZT_STRIDE + 64 * 64) * sizeof(float);
    cudaFuncSetAttribute(mpnn_kernel, cudaFuncAttributeMaxDynamicSharedMemorySize, (int)smem);
    mpnn_kernel<<<4096, 256, smem>>>(fps, adj, emb, W, b, out);
}

// round 3
// speedup vs baseline: 2.0860x; 2.0860x over previous
#include <cuda_runtime.h>
#include <cuda_bf16.h>
#include <cstdint>

// MPNN via mma.sync (HMMA) bf16x3 split. B=4096 graphs, N=64, D=128, L=3.
// CTA = 2 graphs (M=128). Per layer:
//   GEMM1: D1[m,k] = h[m,d] @ W[k,d]^T      (A=h, B=W, K=d)
//   epi1 : z = relu(D1+bias) -> zt[k][m]    (B-operand layout for GEMM2)
//   GEMM2: D2[m,d] = adjI[m,n] @ zt[d][n]^T (A=adjI=I+adj, K=n)
//   epi2 : h <- D2                           [h' = z + adj z = (I+adj) z]
// fp32 operands split x = hi + lo (bf16); 3 HMMA per tile-pair accumulate
// hi*hi + hi*lo + lo*hi into one fp32 register accumulator.

#define SM_AH     0         // h hi  [128 rows][256B]  (32KB)
#define SM_AH_LO  32768     // h lo
#define SM_R2     65536     // W/zt hi
#define SM_R2_LO  98304     // W/zt lo
#define SM_ADJ    131072    // adjI hi
#define SM_ADJ_LO 163840    // adjI lo
#define SM_BIAS   196608    // 128 floats
#define SM_TOTAL  197120

// swizzled byte offset inside a [128][128] bf16 operand (row stride 256B).
// 16B chunk c of row r stored at chunk c ^ (r&7): ldmatrix (8 rows/phase)
// hits 8 distinct 16B slots -> conflict-free.
__device__ __forceinline__ int swz_off(int row, int col) {
    return (row << 8) + ((((col >> 3) ^ (row & 7)) << 4) | ((col & 7) << 1));
}

__device__ __forceinline__ uint32_t smem_u32(const void* p) {
    uint32_t a;
    asm("{ .reg .u64 t; cvta.to.shared.u64 t, %1; cvt.u32.u64 %0, t; }" : "=r"(a) : "l"(p));
    return a;
}

__device__ __forceinline__ void ldsm4(uint32_t* r, uint32_t addr) {
    asm volatile("ldmatrix.sync.aligned.m8n8.x4.shared.b16 {%0,%1,%2,%3}, [%4];"
                 : "=r"(r[0]), "=r"(r[1]), "=r"(r[2]), "=r"(r[3]) : "r"(addr));
}

__device__ __forceinline__ void mma16816(float* c, const uint32_t* a, const uint32_t* b) {
    asm volatile("mma.sync.aligned.m16n8k16.row.col.f32.bf16.bf16.f32 "
                 "{%0,%1,%2,%3}, {%4,%5,%6,%7}, {%8,%9}, {%0,%1,%2,%3};"
                 : "+f"(c[0]), "+f"(c[1]), "+f"(c[2]), "+f"(c[3])
                 : "r"(a[0]), "r"(a[1]), "r"(a[2]), "r"(a[3]), "r"(b[0]), "r"(b[1]));
}

__device__ __forceinline__ void store_split(char* hi, char* lo, int row, int col, float v) {
    int off = swz_off(row, col);
    __nv_bfloat16 h = __float2bfloat16(v);
    *reinterpret_cast<__nv_bfloat16*>(hi + off) = h;
    *reinterpret_cast<__nv_bfloat16*>(lo + off) = __float2bfloat16(v - __bfloat162float(h));
}

// C[128x128] = A[128xK=128] * B[128xK=128]^T, bf16x3, warp tile 32x64.
__device__ __forceinline__ void gemm128(float (&acc)[64],
                                        uint32_t aHiB, uint32_t aLoB,
                                        uint32_t bHiB, uint32_t bLoB,
                                        int m_base, int n_base, int lane)
{
    #pragma unroll
    for (int i = 0; i < 64; i++) acc[i] = 0.0f;

    const int a_row = lane & 15;                         // A ldmatrix row
    const int a_kc  = lane >> 4;                         // A k-chunk 0/1
    const int b_row = ((lane >> 4) << 3) + (lane & 7);   // B sub-tile row
    const int b_kc  = (lane >> 3) & 1;                   // B k-chunk 0/1

    for (int ks = 0; ks < 8; ks++) {
        uint32_t aH[2][4], aL[2][4];
        #pragma unroll
        for (int t = 0; t < 2; t++) {
            int row = m_base + t * 16 + a_row;
            uint32_t off = (row << 8) + ((((ks << 1) + a_kc) ^ (row & 7)) << 4);
            ldsm4(aH[t], aHiB + off);
            ldsm4(aL[t], aLoB + off);
        }
        #pragma unroll
        for (int p = 0; p < 4; p++) {
            int row = n_base + p * 16 + b_row;
            uint32_t off = (row << 8) + ((((ks << 1) + b_kc) ^ (row & 7)) << 4);
            uint32_t bH[4], bL[4];
            ldsm4(bH, bHiB + off);
            ldsm4(bL, bLoB + off);
            #pragma unroll
            for (int t = 0; t < 2; t++)
                #pragma unroll
                for (int s = 0; s < 2; s++) {
                    float* c = &acc[(t * 8 + p * 2 + s) * 4];
                    mma16816(c, aH[t], &bH[2 * s]);
                    mma16816(c, aH[t], &bL[2 * s]);
                    mma16816(c, aL[t], &bH[2 * s]);
                }
        }
    }
}

__global__ __launch_bounds__(256, 1)
void mpnn_hmma_kernel(const int*   __restrict__ fps,
                      const float* __restrict__ adj,
                      const float* __restrict__ emb,
                      const float* __restrict__ W,
                      const float* __restrict__ bias,
                      float*       __restrict__ out)
{
    extern __shared__ char smem[];
    const uint32_t sbase = smem_u32(smem);
    const int tid  = threadIdx.x;
    const int wid  = tid >> 5;
    const int lane = tid & 31;
    const int bid  = blockIdx.x;
    const int m_base = (wid & 3) * 32;     // 4 warps over M
    const int n_base = (wid >> 2) * 64;    // 2 warps over N

    // ---- zero adjI region (hi+lo, 64KB contiguous) ----
    {
        float4 z4 = make_float4(0.f, 0.f, 0.f, 0.f);
        float4* p = reinterpret_cast<float4*>(smem + SM_ADJ);
        #pragma unroll
        for (int i = 0; i < 16; i++) p[tid + (i << 8)] = z4;
    }
    __syncthreads();

    // ---- adjI = I + adj (two 64x64 diagonal blocks) ----
    {
        const float4* ag = reinterpret_cast<const float4*>(adj) + (size_t)bid * 2048;
        #pragma unroll
        for (int i = 0; i < 8; i++) {
            int idx = tid + (i << 8);          // 0..2047 float4s (2 graphs)
            int g   = idx >> 10;
            int rem = idx & 1023;
            int mm  = rem >> 4;
            int nn  = (rem & 15) << 2;
            float4 v = ag[idx];
            int row = (g << 6) + mm;
            int cb  = (g << 6) + nn;
            float vv[4] = { v.x, v.y, v.z, v.w };
            #pragma unroll
            for (int e = 0; e < 4; e++) {
                float val = vv[e] + ((row == cb + e) ? 1.0f : 0.0f);
                store_split(smem + SM_ADJ, smem + SM_ADJ_LO, row, cb + e, val);
            }
        }
    }

    // ---- h0: gather embeddings ----
    {
        int m    = tid >> 1;
        int half = tid & 1;
        int fp   = fps[bid * 128 + m];
        const float4* er = reinterpret_cast<const float4*>(emb) + ((size_t)fp << 5);
        #pragma unroll
        for (int j = 0; j < 16; j++) {
            int c4 = (half << 4) + j;
            float4 v = er[c4];
            int d = c4 << 2;
            store_split(smem + SM_AH, smem + SM_AH_LO, m, d + 0, v.x);
            store_split(smem + SM_AH, smem + SM_AH_LO, m, d + 1, v.y);
            store_split(smem + SM_AH, smem + SM_AH_LO, m, d + 2, v.z);
            store_split(smem + SM_AH, smem + SM_AH_LO, m, d + 3, v.w);
        }
    }

    float* bias_s = reinterpret_cast<float*>(smem + SM_BIAS);

    for (int l = 0; l < 3; l++) {
        __syncthreads();   // zt/adj readers of prev layer done; h0/adj staged (l=0)

        // ---- stage W[l] + bias[l] ----
        {
            const float4* wg = reinterpret_cast<const float4*>(W) + (size_t)l * 4096;
            #pragma unroll
            for (int i = 0; i < 16; i++) {
                int idx = tid + (i << 8);
                int k   = idx >> 5;
                int d   = (idx & 31) << 2;
                float4 v = wg[idx];
                store_split(smem + SM_R2, smem + SM_R2_LO, k, d + 0, v.x);
                store_split(smem + SM_R2, smem + SM_R2_LO, k, d + 1, v.y);
                store_split(smem + SM_R2, smem + SM_R2_LO, k, d + 2, v.z);
                store_split(smem + SM_R2, smem + SM_R2_LO, k, d + 3, v.w);
            }
            if (tid < 128) bias_s[tid] = bias[l * 128 + tid];
        }
        __syncthreads();

        // ---- GEMM1: D1 = h @ W^T ----
        float acc[64];
        gemm128(acc, sbase + SM_AH, sbase + SM_AH_LO,
                     sbase + SM_R2, sbase + SM_R2_LO, m_base, n_base, lane);
        __syncthreads();   // all warps done reading W before zt overwrites it

        // ---- epi1: z = relu(D1 + b) -> zt[k][m] in R2 ----
        #pragma unroll
        for (int t = 0; t < 2; t++)
            #pragma unroll
            for (int nt = 0; nt < 8; nt++) {
                float* c = &acc[(t * 8 + nt) * 4];
                int k0 = n_base + nt * 8 + (lane & 3) * 2;
                int mm = m_base + t * 16 + (lane >> 2);
                #pragma unroll
                for (int r = 0; r < 4; r++) {
                    int k = k0 + (r & 1);
                    int m = mm + (r >> 1) * 8;
                    float v = c[r] + bias_s[k];
                    v = v > 0.0f ? v : 0.0f;
                    store_split(smem + SM_R2, smem + SM_R2_LO, k, m, v);
                }
            }
        __syncthreads();   // zt complete

        // ---- GEMM2: D2 = adjI @ z ----
        gemm128(acc, sbase + SM_ADJ, sbase + SM_ADJ_LO,
                     sbase + SM_R2,  sbase + SM_R2_LO, m_base, n_base, lane);

        // ---- epi2: h' = D2 (bf16 hi/lo, or fp32 on last layer) ----
        #pragma unroll
        for (int t = 0; t < 2; t++)
            #pragma unroll
            for (int nt = 0; nt < 8; nt++) {
                float* c = &acc[(t * 8 + nt) * 4];
                int d0 = n_base + nt * 8 + (lane & 3) * 2;
                int mm = m_base + t * 16 + (lane >> 2);
                if (l < 2) {
                    #pragma unroll
                    for (int rr = 0; rr < 2; rr++) {
                        int m = mm + rr * 8;
                        float v0 = c[rr * 2], v1 = c[rr * 2 + 1];
                        __nv_bfloat16 h0 = __float2bfloat16(v0);
                        __nv_bfloat16 h1 = __float2bfloat16(v1);
                        __nv_bfloat162 hi2 = {h0, h1};
                        __nv_bfloat162 lo2 = {__float2bfloat16(v0 - __bfloat162float(h0)),
                                              __float2bfloat16(v1 - __bfloat162float(h1))};
                        int off = swz_off(m, d0);   // d0 even -> 4B aligned
                        *reinterpret_cast<__nv_bfloat162*>(smem + SM_AH + off)    = hi2;
                        *reinterpret_cast<__nv_bfloat162*>(smem + SM_AH_LO + off) = lo2;
                    }
                } else {
                    float* hb = reinterpret_cast<float*>(smem + SM_AH);
                    #pragma unroll
                    for (int rr = 0; rr < 2; rr++) {
                        int m = mm + rr * 8;
                        *reinterpret_cast<float2*>(hb + m * 128 + d0) =
                            make_float2(c[rr * 2], c[rr * 2 + 1]);
                    }
                }
            }
    }
    __syncthreads();

    // ---- sum pooling: out[g][d] = sum_m h[m][d] ----
    {
        const float* hb = reinterpret_cast<const float*>(smem + SM_AH);
        int g = tid >> 7;
        int d = tid & 127;
        float s = 0.0f;
        #pragma unroll 8
        for (int mm = 0; mm < 64; mm++)
            s += hb[((g << 6) + mm) * 128 + d];
        out[((size_t)bid * 2 + g) * 128 + d] = s;
    }
}

extern "C" void kernel_launch(void* const* d_in, const int* in_sizes, int n_in,
                              void* d_out, int out_size)
{
    (void)in_sizes; (void)n_in; (void)out_size;
    const int*   fps = (const int*)  d_in[0];
    const float* adj = (const float*)d_in[1];
    const float* emb = (const float*)d_in[2];
    const float* W   = (const float*)d_in[3];
    const float* b   = (const float*)d_in[4];
    float*       out = (float*)d_out;

    cudaFuncSetAttribute(mpnn_hmma_kernel, cudaFuncAttributeMaxDynamicSharedMemorySize, SM_TOTAL);
    mpnn_hmma_kernel<<<2048, 256, SM_TOTAL>>>(fps, adj, emb, W, b, out);
}

// round 4
// speedup vs baseline: 3.9692x; 1.9028x over previous
#include <cuda_runtime.h>
#include <cuda_bf16.h>
#include <cstdint>

// MPNN, B=4096 graphs, N=64, D=128, L=3. One graph per CTA (M=64), 2 CTAs/SM.
//   GEMM1: D1[m,k] = h[m,d] @ W[k,d]^T          K=128
//   epi1 : z[m][k] = relu(D1 + b)  (row-major, bf16x2 packed stores)
//   GEMM2: D2[m,d] = adjI[m,n] @ z[n,d]         K=64  (adjI = I + adj)
//   epi2 : h <- D2
// fp32 = hi + lo (bf16, truncated hi); 3 HMMA passes hi*hi + hi*lo + lo*hi.
// Prologue kernels pre-split + pre-swizzle adjI/W/emb into device globals;
// main kernel stages them with linear cp.async (no conversions in hot loop).

// ---- device-global pre-split images (exact smem byte images, swizzled) ----
__device__ __align__(16) unsigned short g_adj_hi[4096 * 4096];  // [g][64r][8ch]
__device__ __align__(16) unsigned short g_adj_lo[4096 * 4096];
__device__ __align__(16) unsigned short g_w_hi[3 * 16384];      // [l][128r][16ch]
__device__ __align__(16) unsigned short g_w_lo[3 * 16384];
__device__ __align__(16) unsigned short g_emb_hi[2048 * 128];   // plain row-major
__device__ __align__(16) unsigned short g_emb_lo[2048 * 128];

// ---- smem layout (112KB / CTA -> 2 CTAs/SM) ----
#define SM_AH     0         // h hi  [64][256B]   16KB
#define SM_AH_LO  16384
#define SM_WZ     32768     // W hi [128][256B] 32KB (z hi [64][256B] aliases)
#define SM_WZ_LO  65536
#define SM_ADJ    98304     // adjI hi [64][128B]  8KB
#define SM_ADJ_LO 106496
#define SM_TOTAL  114688

__device__ __forceinline__ uint32_t smem_u32(const void* p) {
    uint32_t a;
    asm("{ .reg .u64 t; cvta.to.shared.u64 t, %1; cvt.u32.u64 %0, t; }" : "=r"(a) : "l"(p));
    return a;
}
__device__ __forceinline__ void cp16(uint32_t dst, const void* src) {
    asm volatile("cp.async.cg.shared.global [%0], [%1], 16;" :: "r"(dst), "l"(src));
}
#define CP_COMMIT() asm volatile("cp.async.commit_group;" ::: "memory")
#define CP_WAIT0()  asm volatile("cp.async.wait_group 0;" ::: "memory")

__device__ __forceinline__ void ldsm4(uint32_t* r, uint32_t a) {
    asm volatile("ldmatrix.sync.aligned.m8n8.x4.shared.b16 {%0,%1,%2,%3}, [%4];"
                 : "=r"(r[0]), "=r"(r[1]), "=r"(r[2]), "=r"(r[3]) : "r"(a));
}
__device__ __forceinline__ void ldsm4t(uint32_t* r, uint32_t a) {
    asm volatile("ldmatrix.sync.aligned.m8n8.x4.trans.shared.b16 {%0,%1,%2,%3}, [%4];"
                 : "=r"(r[0]), "=r"(r[1]), "=r"(r[2]), "=r"(r[3]) : "r"(a));
}
__device__ __forceinline__ void mma16816(float* c, const uint32_t* a, const uint32_t* b) {
    asm volatile("mma.sync.aligned.m16n8k16.row.col.f32.bf16.bf16.f32 "
                 "{%0,%1,%2,%3}, {%4,%5,%6,%7}, {%8,%9}, {%0,%1,%2,%3};"
                 : "+f"(c[0]), "+f"(c[1]), "+f"(c[2]), "+f"(c[3])
                 : "r"(a[0]), "r"(a[1]), "r"(a[2]), "r"(a[3]), "r"(b[0]), "r"(b[1]));
}
// pack (v0,v1) -> bf16x2 hi (truncated) + bf16x2 lo (rn of residual)
__device__ __forceinline__ void pack_split(float v0, float v1, uint32_t& hi2, uint32_t& lo2) {
    uint32_t b0 = __float_as_uint(v0), b1 = __float_as_uint(v1);
    asm("prmt.b32 %0, %1, %2, 0x7632;" : "=r"(hi2) : "r"(b0), "r"(b1));
    float r0 = v0 - __uint_as_float(b0 & 0xffff0000u);
    float r1 = v1 - __uint_as_float(b1 & 0xffff0000u);
    asm("cvt.rn.bf16x2.f32 %0, %1, %2;" : "=r"(lo2) : "f"(r1), "f"(r0));
}
// swizzled byte offset, 256B-stride region (16 chunks/row, chunk ^= row&7)
__device__ __forceinline__ int swz256(int row, int col) {
    return (row << 8) + ((((col >> 3) ^ (row & 7)) << 4) | ((col & 7) << 1));
}

// GEMM1: C[64x(128)] = h[64x128] @ W[128x128]^T ; warp tile 32x32, K=128
__device__ __forceinline__ void gemm1(float (&acc)[32], uint32_t aHi, uint32_t aLo,
                                      uint32_t bHi, uint32_t bLo,
                                      int m_base, int n_base, int lane) {
    #pragma unroll
    for (int i = 0; i < 32; i++) acc[i] = 0.0f;
    const int a_row = lane & 15, a_kc = lane >> 4;
    const int b_row = ((lane >> 4) << 3) + (lane & 7), b_kc = (lane >> 3) & 1;
    #pragma unroll
    for (int ks = 0; ks < 8; ks++) {
        uint32_t aH[2][4], aL[2][4];
        #pragma unroll
        for (int t = 0; t < 2; t++) {
            int row = m_base + t * 16 + a_row;
            uint32_t off = (row << 8) + ((((ks << 1) + a_kc) ^ (row & 7)) << 4);
            ldsm4(aH[t], aHi + off);
            ldsm4(aL[t], aLo + off);
        }
        #pragma unroll
        for (int p = 0; p < 2; p++) {
            int row = n_base + p * 16 + b_row;
            uint32_t off = (row << 8) + ((((ks << 1) + b_kc) ^ (row & 7)) << 4);
            uint32_t bH[4], bL[4];
            ldsm4(bH, bHi + off);
            ldsm4(bL, bLo + off);
            #pragma unroll
            for (int t = 0; t < 2; t++)
                #pragma unroll
                for (int s = 0; s < 2; s++) {
                    float* c = &acc[(t * 4 + p * 2 + s) * 4];
                    mma16816(c, aH[t], &bH[2 * s]);
                    mma16816(c, aH[t], &bL[2 * s]);
                    mma16816(c, aL[t], &bH[2 * s]);
                }
        }
    }
}

// GEMM2: C[64x(128)] = adjI[64x64] @ z[64x128]; A stride 128B, B via ldmatrix.trans
__device__ __forceinline__ void gemm2(float (&acc)[32], uint32_t aHi, uint32_t aLo,
                                      uint32_t zHi, uint32_t zLo,
                                      int m_base, int n_base, int lane) {
    #pragma unroll
    for (int i = 0; i < 32; i++) acc[i] = 0.0f;
    const int a_row = lane & 15, a_kc = lane >> 4;
    const int grp = lane >> 3, r = lane & 7;
    #pragma unroll
    for (int ks = 0; ks < 4; ks++) {
        uint32_t aH[2][4], aL[2][4];
        #pragma unroll
        for (int t = 0; t < 2; t++) {
            int row = m_base + t * 16 + a_row;
            uint32_t off = (row << 7) + ((((ks << 1) + a_kc) ^ (row & 7)) << 4);
            ldsm4(aH[t], aHi + off);
            ldsm4(aL[t], aLo + off);
        }
        int row_b = (ks << 4) + ((grp & 1) << 3) + r;   // z row = n
        #pragma unroll
        for (int p = 0; p < 2; p++) {
            int cc = ((n_base + p * 16) >> 3) + (grp >> 1);
            uint32_t off = (row_b << 8) + ((cc ^ (row_b & 7)) << 4);
            uint32_t bH[4], bL[4];
            ldsm4t(bH, zHi + off);
            ldsm4t(bL, zLo + off);
            #pragma unroll
            for (int t = 0; t < 2; t++)
                #pragma unroll
                for (int s = 0; s < 2; s++) {
                    float* c = &acc[(t * 4 + p * 2 + s) * 4];
                    mma16816(c, aH[t], &bH[2 * s]);
                    mma16816(c, aH[t], &bL[2 * s]);
                    mma16816(c, aL[t], &bH[2 * s]);
                }
        }
    }
}

// ---------------- prologue kernels ----------------
__global__ void prep_adj(const float* __restrict__ adj) {
    int g = blockIdx.x;
    #pragma unroll
    for (int i = 0; i < 16; i++) {
        int idx = threadIdx.x + (i << 8);         // 0..4095
        int row = idx >> 6, col = idx & 63;
        float v = adj[(size_t)g * 4096 + idx] + (row == col ? 1.0f : 0.0f);
        uint32_t b = __float_as_uint(v);
        float lo = v - __uint_as_float(b & 0xffff0000u);
        size_t pos = (size_t)g * 4096 + row * 64 + (((col >> 3) ^ (row & 7)) << 3) + (col & 7);
        g_adj_hi[pos] = (unsigned short)(b >> 16);
        g_adj_lo[pos] = __bfloat16_as_ushort(__float2bfloat16(lo));
    }
}
__global__ void prep_w(const float* __restrict__ W) {
    int idx = blockIdx.x * 256 + threadIdx.x;     // grid 192 -> 49152
    int l = idx >> 14, rem = idx & 16383;
    int row = rem >> 7, col = rem & 127;
    float v = W[idx];
    uint32_t b = __float_as_uint(v);
    float lo = v - __uint_as_float(b & 0xffff0000u);
    int pos = l * 16384 + row * 128 + (((col >> 3) ^ (row & 7)) << 3) + (col & 7);
    g_w_hi[pos] = (unsigned short)(b >> 16);
    g_w_lo[pos] = __bfloat16_as_ushort(__float2bfloat16(lo));
}
__global__ void prep_emb(const float* __restrict__ emb) {
    int base = (blockIdx.x * 256 + threadIdx.x) * 4;   // grid 256 -> 262144
    float4 v = *reinterpret_cast<const float4*>(emb + base);
    float vv[4] = { v.x, v.y, v.z, v.w };
    #pragma unroll
    for (int e = 0; e < 4; e++) {
        uint32_t b = __float_as_uint(vv[e]);
        float lo = vv[e] - __uint_as_float(b & 0xffff0000u);
        g_emb_hi[base + e] = (unsigned short)(b >> 16);
        g_emb_lo[base + e] = __bfloat16_as_ushort(__float2bfloat16(lo));
    }
}

// ---------------- main kernel ----------------
__global__ __launch_bounds__(256, 2)
void mpnn_main(const int* __restrict__ fps,
               const float* __restrict__ bias,
               float* __restrict__ out)
{
    extern __shared__ char smem[];
    const uint32_t sb = smem_u32(smem);
    const int tid = threadIdx.x, wid = tid >> 5, lane = tid & 31;
    const int bid = blockIdx.x;
    const int m_base = (wid & 1) << 5;     // 0 / 32
    const int n_base = (wid >> 1) << 5;    // 0,32,64,96

    // ---- stage adjI (linear image copy) + emb (gather rows) ----
    #pragma unroll
    for (int i = 0; i < 4; i++) {
        int idx = tid + (i << 8);                  // 0..1023
        int buf = idx >> 9, rem = idx & 511;
        const unsigned short* src = (buf ? g_adj_lo : g_adj_hi) + (size_t)bid * 4096 + rem * 8;
        cp16(sb + SM_ADJ + buf * 8192 + rem * 16, src);
    }
    #pragma unroll
    for (int i = 0; i < 8; i++) {
        int idx = tid + (i << 8);                  // 0..2047
        int buf = idx >> 10, rem = idx & 1023;
        int m = rem >> 4, c = rem & 15;
        int fp = fps[(bid << 6) + m];
        const unsigned short* src = (buf ? g_emb_lo : g_emb_hi) + (size_t)fp * 128 + c * 8;
        cp16(sb + SM_AH + buf * 16384 + (m << 8) + (((c ^ (m & 7))) << 4), src);
    }

    for (int l = 0; l < 3; l++) {
        // ---- stage W[l] (linear image copy into WZ; z of prev layer dead) ----
        #pragma unroll
        for (int i = 0; i < 16; i++) {
            int idx = tid + (i << 8);              // 0..4095
            int buf = idx >> 11, rem = idx & 2047;
            const unsigned short* src = (buf ? g_w_lo : g_w_hi) + l * 16384 + rem * 8;
            cp16(sb + SM_WZ + buf * 32768 + rem * 16, src);
        }
        CP_COMMIT();
        CP_WAIT0();
        __syncthreads();

        float acc[32];
        // ---- GEMM1 ----
        gemm1(acc, sb + SM_AH, sb + SM_AH_LO, sb + SM_WZ, sb + SM_WZ_LO,
              m_base, n_base, lane);
        __syncthreads();   // all warps done reading W before z overwrites

        // ---- epi1: z = relu(D1+b) -> z[m][k] row-major in WZ ----
        #pragma unroll
        for (int t = 0; t < 2; t++)
            #pragma unroll
            for (int nt = 0; nt < 4; nt++) {
                float* c = &acc[(t * 4 + nt) * 4];
                int k0 = n_base + nt * 8 + (lane & 3) * 2;
                int m  = m_base + t * 16 + (lane >> 2);
                float b0 = __ldg(bias + l * 128 + k0);
                float b1 = __ldg(bias + l * 128 + k0 + 1);
                float v0 = fmaxf(c[0] + b0, 0.0f), v1 = fmaxf(c[1] + b1, 0.0f);
                float v2 = fmaxf(c[2] + b0, 0.0f), v3 = fmaxf(c[3] + b1, 0.0f);
                uint32_t hi2, lo2;
                pack_split(v0, v1, hi2, lo2);
                int off = swz256(m, k0);
                *reinterpret_cast<uint32_t*>(smem + SM_WZ + off)    = hi2;
                *reinterpret_cast<uint32_t*>(smem + SM_WZ_LO + off) = lo2;
                pack_split(v2, v3, hi2, lo2);
                off = swz256(m + 8, k0);
                *reinterpret_cast<uint32_t*>(smem + SM_WZ + off)    = hi2;
                *reinterpret_cast<uint32_t*>(smem + SM_WZ_LO + off) = lo2;
            }
        __syncthreads();

        // ---- GEMM2: D2 = adjI @ z ----
        gemm2(acc, sb + SM_ADJ, sb + SM_ADJ_LO, sb + SM_WZ, sb + SM_WZ_LO,
              m_base, n_base, lane);

        // ---- epi2 ----
        #pragma unroll
        for (int t = 0; t < 2; t++)
            #pragma unroll
            for (int nt = 0; nt < 4; nt++) {
                float* c = &acc[(t * 4 + nt) * 4];
                int d0 = n_base + nt * 8 + (lane & 3) * 2;
                int m  = m_base + t * 16 + (lane >> 2);
                if (l < 2) {
                    uint32_t hi2, lo2;
                    pack_split(c[0], c[1], hi2, lo2);
                    int off = swz256(m, d0);
                    *reinterpret_cast<uint32_t*>(smem + SM_AH + off)    = hi2;
                    *reinterpret_cast<uint32_t*>(smem + SM_AH_LO + off) = lo2;
                    pack_split(c[2], c[3], hi2, lo2);
                    off = swz256(m + 8, d0);
                    *reinterpret_cast<uint32_t*>(smem + SM_AH + off)    = hi2;
                    *reinterpret_cast<uint32_t*>(smem + SM_AH_LO + off) = lo2;
                } else {
                    float* pool = reinterpret_cast<float*>(smem);       // 64x128 fp32
                    *reinterpret_cast<float2*>(pool + m * 128 + d0)       = make_float2(c[0], c[1]);
                    *reinterpret_cast<float2*>(pool + (m + 8) * 128 + d0) = make_float2(c[2], c[3]);
                }
            }
        __syncthreads();
    }

    // ---- sum pooling: out[bid][d] = sum_m h[m][d] ----
    if (tid < 128) {
        const float* pool = reinterpret_cast<const float*>(smem);
        float s = 0.0f;
        #pragma unroll 8
        for (int mm = 0; mm < 64; mm++) s += pool[mm * 128 + tid];
        out[(size_t)bid * 128 + tid] = s;
    }
}

extern "C" void kernel_launch(void* const* d_in, const int* in_sizes, int n_in,
                              void* d_out, int out_size)
{
    (void)in_sizes; (void)n_in; (void)out_size;
    const int*   fps = (const int*)  d_in[0];
    const float* adj = (const float*)d_in[1];
    const float* emb = (const float*)d_in[2];
    const float* W   = (const float*)d_in[3];
    const float* b   = (const float*)d_in[4];
    float*       out = (float*)d_out;

    prep_adj<<<4096, 256>>>(adj);
    prep_w<<<192, 256>>>(W);
    prep_emb<<<256, 256>>>(emb);

    cudaFuncSetAttribute(mpnn_main, cudaFuncAttributeMaxDynamicSharedMemorySize, SM_TOTAL);
    mpnn_main<<<4096, 256, SM_TOTAL>>>(fps, b, out);
}

// round 5
// speedup vs baseline: 4.5054x; 1.1351x over previous
#include <cuda_runtime.h>
#include <cuda_bf16.h>
#include <cstdint>

// MPNN, B=4096 graphs, N=64, D=128, L=3. One graph per CTA (M=64), 2 CTAs/SM.
//   GEMM1: D1[m,k] = h[m,d] @ W[k,d]^T          K=128
//   epi1 : z[m][k] = relu(D1 + b)  (row-major, bf16x2 packed stores)
//   GEMM2: D2[m,d] = adjI[m,n] @ z[n,d]         K=64  (adjI = I + adj)
//   epi2 : h <- D2
// fp32 = hi + lo (bf16, truncated hi); 3 HMMA passes hi*hi + hi*lo + lo*hi.
// W/emb pre-split+pre-swizzled by tiny prologue kernels; adj is split
// INSIDE the main kernel (overlapped with cp.async waits / co-CTA MMA).

__device__ __align__(16) unsigned short g_w_hi[3 * 16384];      // [l][128r][16ch]
__device__ __align__(16) unsigned short g_w_lo[3 * 16384];
__device__ __align__(16) unsigned short g_emb_hi[2048 * 128];   // row-major
__device__ __align__(16) unsigned short g_emb_lo[2048 * 128];

// ---- smem layout (112KB / CTA -> 2 CTAs/SM) ----
#define SM_AH     0         // h hi  [64][256B]   16KB   (fp32 pool on last layer)
#define SM_AH_LO  16384
#define SM_WZ     32768     // W hi [128][256B] 32KB (z hi [64][256B] aliases)
#define SM_WZ_LO  65536
#define SM_ADJ    98304     // adjI hi [64][128B]  8KB
#define SM_ADJ_LO 106496
#define SM_TOTAL  114688

__device__ __forceinline__ uint32_t smem_u32(const void* p) {
    uint32_t a;
    asm("{ .reg .u64 t; cvta.to.shared.u64 t, %1; cvt.u32.u64 %0, t; }" : "=r"(a) : "l"(p));
    return a;
}
__device__ __forceinline__ void cp16(uint32_t dst, const void* src) {
    asm volatile("cp.async.cg.shared.global [%0], [%1], 16;" :: "r"(dst), "l"(src));
}
#define CP_COMMIT() asm volatile("cp.async.commit_group;" ::: "memory")
#define CP_WAIT0()  asm volatile("cp.async.wait_group 0;" ::: "memory")

__device__ __forceinline__ void ldsm4(uint32_t* r, uint32_t a) {
    asm volatile("ldmatrix.sync.aligned.m8n8.x4.shared.b16 {%0,%1,%2,%3}, [%4];"
                 : "=r"(r[0]), "=r"(r[1]), "=r"(r[2]), "=r"(r[3]) : "r"(a));
}
__device__ __forceinline__ void ldsm4t(uint32_t* r, uint32_t a) {
    asm volatile("ldmatrix.sync.aligned.m8n8.x4.trans.shared.b16 {%0,%1,%2,%3}, [%4];"
                 : "=r"(r[0]), "=r"(r[1]), "=r"(r[2]), "=r"(r[3]) : "r"(a));
}
__device__ __forceinline__ void mma16816(float* c, const uint32_t* a, const uint32_t* b) {
    asm volatile("mma.sync.aligned.m16n8k16.row.col.f32.bf16.bf16.f32 "
                 "{%0,%1,%2,%3}, {%4,%5,%6,%7}, {%8,%9}, {%0,%1,%2,%3};"
                 : "+f"(c[0]), "+f"(c[1]), "+f"(c[2]), "+f"(c[3])
                 : "r"(a[0]), "r"(a[1]), "r"(a[2]), "r"(a[3]), "r"(b[0]), "r"(b[1]));
}
// pack (v0,v1) -> bf16x2 hi (truncated) + bf16x2 lo (rn of residual)
__device__ __forceinline__ void pack_split(float v0, float v1, uint32_t& hi2, uint32_t& lo2) {
    uint32_t b0 = __float_as_uint(v0), b1 = __float_as_uint(v1);
    asm("prmt.b32 %0, %1, %2, 0x7632;" : "=r"(hi2) : "r"(b0), "r"(b1));
    float r0 = v0 - __uint_as_float(b0 & 0xffff0000u);
    float r1 = v1 - __uint_as_float(b1 & 0xffff0000u);
    asm("cvt.rn.bf16x2.f32 %0, %1, %2;" : "=r"(lo2) : "f"(r1), "f"(r0));
}
// swizzled byte offset, 256B-stride region (16 chunks/row, chunk ^= row&7)
__device__ __forceinline__ int swz256(int row, int col) {
    return (row << 8) + ((((col >> 3) ^ (row & 7)) << 4) | ((col & 7) << 1));
}

// GEMM1: C[64x128] = h[64x128] @ W[128x128]^T ; warp tile 32x32, K=128
__device__ __forceinline__ void gemm1(float (&acc)[32], uint32_t aHi, uint32_t aLo,
                                      uint32_t bHi, uint32_t bLo,
                                      int m_base, int n_base, int lane) {
    #pragma unroll
    for (int i = 0; i < 32; i++) acc[i] = 0.0f;
    const int a_row = lane & 15, a_kc = lane >> 4;
    const int b_row = ((lane >> 4) << 3) + (lane & 7), b_kc = (lane >> 3) & 1;
    #pragma unroll
    for (int ks = 0; ks < 8; ks++) {
        uint32_t aH[2][4], aL[2][4];
        #pragma unroll
        for (int t = 0; t < 2; t++) {
            int row = m_base + t * 16 + a_row;
            uint32_t off = (row << 8) + ((((ks << 1) + a_kc) ^ (row & 7)) << 4);
            ldsm4(aH[t], aHi + off);
            ldsm4(aL[t], aLo + off);
        }
        #pragma unroll
        for (int p = 0; p < 2; p++) {
            int row = n_base + p * 16 + b_row;
            uint32_t off = (row << 8) + ((((ks << 1) + b_kc) ^ (row & 7)) << 4);
            uint32_t bH[4], bL[4];
            ldsm4(bH, bHi + off);
            ldsm4(bL, bLo + off);
            #pragma unroll
            for (int t = 0; t < 2; t++)
                #pragma unroll
                for (int s = 0; s < 2; s++) {
                    float* c = &acc[(t * 4 + p * 2 + s) * 4];
                    mma16816(c, aH[t], &bH[2 * s]);
                    mma16816(c, aH[t], &bL[2 * s]);
                    mma16816(c, aL[t], &bH[2 * s]);
                }
        }
    }
}

// GEMM2: C[64x128] = adjI[64x64] @ z[64x128]; A stride 128B, B via ldmatrix.trans
__device__ __forceinline__ void gemm2(float (&acc)[32], uint32_t aHi, uint32_t aLo,
                                      uint32_t zHi, uint32_t zLo,
                                      int m_base, int n_base, int lane) {
    #pragma unroll
    for (int i = 0; i < 32; i++) acc[i] = 0.0f;
    const int a_row = lane & 15, a_kc = lane >> 4;
    const int grp = lane >> 3, r = lane & 7;
    #pragma unroll
    for (int ks = 0; ks < 4; ks++) {
        uint32_t aH[2][4], aL[2][4];
        #pragma unroll
        for (int t = 0; t < 2; t++) {
            int row = m_base + t * 16 + a_row;
            uint32_t off = (row << 7) + ((((ks << 1) + a_kc) ^ (row & 7)) << 4);
            ldsm4(aH[t], aHi + off);
            ldsm4(aL[t], aLo + off);
        }
        int row_b = (ks << 4) + ((grp & 1) << 3) + r;   // z row = n
        #pragma unroll
        for (int p = 0; p < 2; p++) {
            int cc = ((n_base + p * 16) >> 3) + (grp >> 1);
            uint32_t off = (row_b << 8) + ((cc ^ (row_b & 7)) << 4);
            uint32_t bH[4], bL[4];
            ldsm4t(bH, zHi + off);
            ldsm4t(bL, zLo + off);
            #pragma unroll
            for (int t = 0; t < 2; t++)
                #pragma unroll
                for (int s = 0; s < 2; s++) {
                    float* c = &acc[(t * 4 + p * 2 + s) * 4];
                    mma16816(c, aH[t], &bH[2 * s]);
                    mma16816(c, aH[t], &bL[2 * s]);
                    mma16816(c, aL[t], &bH[2 * s]);
                }
        }
    }
}

// ---------------- prologue kernels (tiny) ----------------
__global__ void prep_w(const float* __restrict__ W) {
    int idx = blockIdx.x * 256 + threadIdx.x;     // grid 192 -> 49152
    int l = idx >> 14, rem = idx & 16383;
    int row = rem >> 7, col = rem & 127;
    float v = W[idx];
    uint32_t b = __float_as_uint(v);
    float lo = v - __uint_as_float(b & 0xffff0000u);
    int pos = l * 16384 + row * 128 + (((col >> 3) ^ (row & 7)) << 3) + (col & 7);
    g_w_hi[pos] = (unsigned short)(b >> 16);
    g_w_lo[pos] = __bfloat16_as_ushort(__float2bfloat16(lo));
}
__global__ void prep_emb(const float* __restrict__ emb) {
    int base = (blockIdx.x * 256 + threadIdx.x) * 4;   // grid 256 -> 262144
    float4 v = *reinterpret_cast<const float4*>(emb + base);
    float vv[4] = { v.x, v.y, v.z, v.w };
    #pragma unroll
    for (int e = 0; e < 4; e++) {
        uint32_t b = __float_as_uint(vv[e]);
        float lo = vv[e] - __uint_as_float(b & 0xffff0000u);
        g_emb_hi[base + e] = (unsigned short)(b >> 16);
        g_emb_lo[base + e] = __bfloat16_as_ushort(__float2bfloat16(lo));
    }
}

// ---------------- main kernel ----------------
__global__ __launch_bounds__(256, 2)
void mpnn_main(const int* __restrict__ fps,
               const float* __restrict__ adj,
               const float* __restrict__ bias,
               float* __restrict__ out)
{
    extern __shared__ char smem[];
    const uint32_t sb = smem_u32(smem);
    const int tid = threadIdx.x, wid = tid >> 5, lane = tid & 31;
    const int bid = blockIdx.x;
    const int m_base = (wid & 1) << 5;     // 0 / 32
    const int n_base = (wid >> 1) << 5;    // 0,32,64,96

    // ---- issue emb gather (cp.async, committed with W(0) below) ----
    #pragma unroll
    for (int i = 0; i < 8; i++) {
        int idx = tid + (i << 8);                  // 0..2047
        int buf = idx >> 10, rem = idx & 1023;
        int m = rem >> 4, c = rem & 15;
        int fp = fps[(bid << 6) + m];
        const unsigned short* src = (buf ? g_emb_lo : g_emb_hi) + (size_t)fp * 128 + c * 8;
        cp16(sb + SM_AH + buf * 16384 + (m << 8) + (((c ^ (m & 7))) << 4), src);
    }

    // ---- adjI = I + adj: fp32 LDG -> hi/lo split -> swizzled STS (in-kernel) ----
    {
        const float4* ag = reinterpret_cast<const float4*>(adj) + (size_t)bid * 1024;
        #pragma unroll
        for (int i = 0; i < 4; i++) {
            int q   = tid + (i << 8);              // float4 idx 0..1023
            int row = q >> 4;
            int c4  = (q & 15) << 2;               // col base (mult of 4)
            float4 v = ag[q];
            float a0 = v.x + ((row == c4 + 0) ? 1.0f : 0.0f);
            float a1 = v.y + ((row == c4 + 1) ? 1.0f : 0.0f);
            float a2 = v.z + ((row == c4 + 2) ? 1.0f : 0.0f);
            float a3 = v.w + ((row == c4 + 3) ? 1.0f : 0.0f);
            uint32_t h0, l0, h1, l1;
            pack_split(a0, a1, h0, l0);
            pack_split(a2, a3, h1, l1);
            // 128B-stride swizzle: chunk (col>>3) ^ (row&7), byte (col&7)*2
            int off = (row << 7) + ((((c4 >> 3) ^ (row & 7)) << 4) | ((c4 & 7) << 1));
            *reinterpret_cast<uint32_t*>(smem + SM_ADJ + off)        = h0;
            *reinterpret_cast<uint32_t*>(smem + SM_ADJ + off + 4)    = h1;
            *reinterpret_cast<uint32_t*>(smem + SM_ADJ_LO + off)     = l0;
            *reinterpret_cast<uint32_t*>(smem + SM_ADJ_LO + off + 4) = l1;
        }
    }

    for (int l = 0; l < 3; l++) {
        // ---- stage W[l] (linear image copy into WZ; z of prev layer dead) ----
        #pragma unroll
        for (int i = 0; i < 16; i++) {
            int idx = tid + (i << 8);              // 0..4095
            int buf = idx >> 11, rem = idx & 2047;
            const unsigned short* src = (buf ? g_w_lo : g_w_hi) + l * 16384 + rem * 8;
            cp16(sb + SM_WZ + buf * 32768 + rem * 16, src);
        }
        CP_COMMIT();
        CP_WAIT0();
        __syncthreads();

        float acc[32];
        // ---- GEMM1 ----
        gemm1(acc, sb + SM_AH, sb + SM_AH_LO, sb + SM_WZ, sb + SM_WZ_LO,
              m_base, n_base, lane);
        __syncthreads();   // all warps done reading W before z overwrites

        // ---- epi1: z = relu(D1+b) -> z[m][k] row-major in WZ ----
        #pragma unroll
        for (int t = 0; t < 2; t++)
            #pragma unroll
            for (int nt = 0; nt < 4; nt++) {
                float* c = &acc[(t * 4 + nt) * 4];
                int k0 = n_base + nt * 8 + (lane & 3) * 2;
                int m  = m_base + t * 16 + (lane >> 2);
                float b0 = __ldg(bias + l * 128 + k0);
                float b1 = __ldg(bias + l * 128 + k0 + 1);
                float v0 = fmaxf(c[0] + b0, 0.0f), v1 = fmaxf(c[1] + b1, 0.0f);
                float v2 = fmaxf(c[2] + b0, 0.0f), v3 = fmaxf(c[3] + b1, 0.0f);
                uint32_t hi2, lo2;
                pack_split(v0, v1, hi2, lo2);
                int off = swz256(m, k0);
                *reinterpret_cast<uint32_t*>(smem + SM_WZ + off)    = hi2;
                *reinterpret_cast<uint32_t*>(smem + SM_WZ_LO + off) = lo2;
                pack_split(v2, v3, hi2, lo2);
                off = swz256(m + 8, k0);
                *reinterpret_cast<uint32_t*>(smem + SM_WZ + off)    = hi2;
                *reinterpret_cast<uint32_t*>(smem + SM_WZ_LO + off) = lo2;
            }
        __syncthreads();

        // ---- GEMM2: D2 = adjI @ z ----
        gemm2(acc, sb + SM_ADJ, sb + SM_ADJ_LO, sb + SM_WZ, sb + SM_WZ_LO,
              m_base, n_base, lane);

        // ---- epi2: h' = D2 (hi/lo, or swizzled fp32 pool on last layer) ----
        #pragma unroll
        for (int t = 0; t < 2; t++)
            #pragma unroll
            for (int nt = 0; nt < 4; nt++) {
                float* c = &acc[(t * 4 + nt) * 4];
                int d0 = n_base + nt * 8 + (lane & 3) * 2;
                int m  = m_base + t * 16 + (lane >> 2);
                if (l < 2) {
                    uint32_t hi2, lo2;
                    pack_split(c[0], c[1], hi2, lo2);
                    int off = swz256(m, d0);
                    *reinterpret_cast<uint32_t*>(smem + SM_AH + off)    = hi2;
                    *reinterpret_cast<uint32_t*>(smem + SM_AH_LO + off) = lo2;
                    pack_split(c[2], c[3], hi2, lo2);
                    off = swz256(m + 8, d0);
                    *reinterpret_cast<uint32_t*>(smem + SM_AH + off)    = hi2;
                    *reinterpret_cast<uint32_t*>(smem + SM_AH_LO + off) = lo2;
                } else {
                    // fp32 pool, chunk-XOR swizzled: float index
                    //   m*128 + (((d>>3)^(m&7))<<3) + (d&7)   (conflict-free)
                    float* pool = reinterpret_cast<float*>(smem);
                    int fo0 = (m << 7) + ((((d0 >> 3) ^ (m & 7)) << 3) | (d0 & 7));
                    int m2 = m + 8;
                    int fo1 = (m2 << 7) + ((((d0 >> 3) ^ (m2 & 7)) << 3) | (d0 & 7));
                    *reinterpret_cast<float2*>(pool + fo0) = make_float2(c[0], c[1]);
                    *reinterpret_cast<float2*>(pool + fo1) = make_float2(c[2], c[3]);
                }
            }
        __syncthreads();
    }

    // ---- sum pooling: out[bid][d] = sum_m h[m][d] (de-swizzled reads) ----
    if (tid < 128) {
        const float* pool = reinterpret_cast<const float*>(smem);
        int dc = tid >> 3, dr = tid & 7;
        float s = 0.0f;
        #pragma unroll 8
        for (int mm = 0; mm < 64; mm++)
            s += pool[(mm << 7) + (((dc ^ (mm & 7)) << 3) | dr)];
        out[(size_t)bid * 128 + tid] = s;
    }
}

extern "C" void kernel_launch(void* const* d_in, const int* in_sizes, int n_in,
                              void* d_out, int out_size)
{
    (void)in_sizes; (void)n_in; (void)out_size;
    const int*   fps = (const int*)  d_in[0];
    const float* adj = (const float*)d_in[1];
    const float* emb = (const float*)d_in[2];
    const float* W   = (const float*)d_in[3];
    const float* b   = (const float*)d_in[4];
    float*       out = (float*)d_out;

    prep_w<<<192, 256>>>(W);
    prep_emb<<<256, 256>>>(emb);

    cudaFuncSetAttribute(mpnn_main, cudaFuncAttributeMaxDynamicSharedMemorySize, SM_TOTAL);
    mpnn_main<<<4096, 256, SM_TOTAL>>>(fps, adj, b, out);
}

// round 7
// speedup vs baseline: 4.7569x; 1.0558x over previous
#include <cuda_runtime.h>
#include <cuda_bf16.h>
#include <cstdint>

// MPNN, B=4096 graphs, N=64, D=128, L=3. One graph per CTA (M=64), 2 CTAs/SM.
// Layers 1,2: GEMM1 (h@W^T) -> epi1 (relu+bias -> z) -> GEMM2 (adjI@z) -> h.
// Layer 3:    GEMM1 -> FUSED pooled epilogue:
//   out[k] = sum_m w_m * relu(D1[m,k]+b[k]),  w = 1 + colsum(adj)
//   (because sum_m (z + adj z)[m,k] = sum_n (1+colsum_n) z[n,k])
// fp32 = hi + lo (bf16, truncated hi); 3 HMMA passes hi*hi + hi*lo + lo*hi.

__device__ __align__(16) unsigned short g_w_hi[3 * 16384];   // [l][128r][16ch] swizzled
__device__ __align__(16) unsigned short g_w_lo[3 * 16384];
__device__ __align__(16) unsigned short g_emb_hi[2048 * 128]; // row-major
__device__ __align__(16) unsigned short g_emb_lo[2048 * 128];

// ---- smem layout (112KB / CTA -> 2 CTAs/SM) ----
#define SM_AH     0         // h hi [64][256B] 16KB
#define SM_AH_LO  16384
#define SM_WZ     32768     // W hi [128][256B] 32KB (z hi [64][256B] aliases; colsum scratch at start)
#define SM_WZ_LO  65536
#define SM_ADJ    98304     // adjI hi [64][128B] 8KB (pool scratch at the very end)
#define SM_ADJ_LO 106496
#define SM_TOTAL  114688

__device__ __forceinline__ uint32_t smem_u32(const void* p) {
    uint32_t a;
    asm("{ .reg .u64 t; cvta.to.shared.u64 t, %1; cvt.u32.u64 %0, t; }" : "=r"(a) : "l"(p));
    return a;
}
__device__ __forceinline__ void cp16(uint32_t dst, const void* src) {
    asm volatile("cp.async.cg.shared.global [%0], [%1], 16;" :: "r"(dst), "l"(src));
}
#define CP_COMMIT() asm volatile("cp.async.commit_group;" ::: "memory")
#define CP_WAIT0()  asm volatile("cp.async.wait_group 0;" ::: "memory")

__device__ __forceinline__ void ldsm4(uint32_t* r, uint32_t a) {
    asm volatile("ldmatrix.sync.aligned.m8n8.x4.shared.b16 {%0,%1,%2,%3}, [%4];"
                 : "=r"(r[0]), "=r"(r[1]), "=r"(r[2]), "=r"(r[3]) : "r"(a));
}
__device__ __forceinline__ void ldsm4t(uint32_t* r, uint32_t a) {
    asm volatile("ldmatrix.sync.aligned.m8n8.x4.trans.shared.b16 {%0,%1,%2,%3}, [%4];"
                 : "=r"(r[0]), "=r"(r[1]), "=r"(r[2]), "=r"(r[3]) : "r"(a));
}
__device__ __forceinline__ void mma16816(float* c, const uint32_t* a, const uint32_t* b) {
    asm volatile("mma.sync.aligned.m16n8k16.row.col.f32.bf16.bf16.f32 "
                 "{%0,%1,%2,%3}, {%4,%5,%6,%7}, {%8,%9}, {%0,%1,%2,%3};"
                 : "+f"(c[0]), "+f"(c[1]), "+f"(c[2]), "+f"(c[3])
                 : "r"(a[0]), "r"(a[1]), "r"(a[2]), "r"(a[3]), "r"(b[0]), "r"(b[1]));
}
__device__ __forceinline__ void pack_split(float v0, float v1, uint32_t& hi2, uint32_t& lo2) {
    uint32_t b0 = __float_as_uint(v0), b1 = __float_as_uint(v1);
    asm("prmt.b32 %0, %1, %2, 0x7632;" : "=r"(hi2) : "r"(b0), "r"(b1));
    float r0 = v0 - __uint_as_float(b0 & 0xffff0000u);
    float r1 = v1 - __uint_as_float(b1 & 0xffff0000u);
    asm("cvt.rn.bf16x2.f32 %0, %1, %2;" : "=r"(lo2) : "f"(r1), "f"(r0));
}
__device__ __forceinline__ int swz256(int row, int col) {
    return (row << 8) + ((((col >> 3) ^ (row & 7)) << 4) | ((col & 7) << 1));
}

// GEMM1: C[64x128] = h[64x128] @ W[128x128]^T ; warp tile 32x32, K=128
__device__ __forceinline__ void gemm1(float (&acc)[32], uint32_t aHi, uint32_t aLo,
                                      uint32_t bHi, uint32_t bLo,
                                      int m_base, int n_base, int lane) {
    #pragma unroll
    for (int i = 0; i < 32; i++) acc[i] = 0.0f;
    const int a_row = lane & 15, a_kc = lane >> 4;
    const int b_row = ((lane >> 4) << 3) + (lane & 7), b_kc = (lane >> 3) & 1;
    #pragma unroll
    for (int ks = 0; ks < 8; ks++) {
        uint32_t aH[2][4], aL[2][4];
        #pragma unroll
        for (int t = 0; t < 2; t++) {
            int row = m_base + t * 16 + a_row;
            uint32_t off = (row << 8) + ((((ks << 1) + a_kc) ^ (row & 7)) << 4);
            ldsm4(aH[t], aHi + off);
            ldsm4(aL[t], aLo + off);
        }
        #pragma unroll
        for (int p = 0; p < 2; p++) {
            int row = n_base + p * 16 + b_row;
            uint32_t off = (row << 8) + ((((ks << 1) + b_kc) ^ (row & 7)) << 4);
            uint32_t bH[4], bL[4];
            ldsm4(bH, bHi + off);
            ldsm4(bL, bLo + off);
            #pragma unroll
            for (int t = 0; t < 2; t++)
                #pragma unroll
                for (int s = 0; s < 2; s++) {
                    float* c = &acc[(t * 4 + p * 2 + s) * 4];
                    mma16816(c, aH[t], &bH[2 * s]);
                    mma16816(c, aH[t], &bL[2 * s]);
                    mma16816(c, aL[t], &bH[2 * s]);
                }
        }
    }
}

// GEMM2: C[64x128] = adjI[64x64] @ z[64x128]; A stride 128B, B via ldmatrix.trans
__device__ __forceinline__ void gemm2(float (&acc)[32], uint32_t aHi, uint32_t aLo,
                                      uint32_t zHi, uint32_t zLo,
                                      int m_base, int n_base, int lane) {
    #pragma unroll
    for (int i = 0; i < 32; i++) acc[i] = 0.0f;
    const int a_row = lane & 15, a_kc = lane >> 4;
    const int grp = lane >> 3, r = lane & 7;
    #pragma unroll
    for (int ks = 0; ks < 4; ks++) {
        uint32_t aH[2][4], aL[2][4];
        #pragma unroll
        for (int t = 0; t < 2; t++) {
            int row = m_base + t * 16 + a_row;
            uint32_t off = (row << 7) + ((((ks << 1) + a_kc) ^ (row & 7)) << 4);
            ldsm4(aH[t], aHi + off);
            ldsm4(aL[t], aLo + off);
        }
        int row_b = (ks << 4) + ((grp & 1) << 3) + r;
        #pragma unroll
        for (int p = 0; p < 2; p++) {
            int cc = ((n_base + p * 16) >> 3) + (grp >> 1);
            uint32_t off = (row_b << 8) + ((cc ^ (row_b & 7)) << 4);
            uint32_t bH[4], bL[4];
            ldsm4t(bH, zHi + off);
            ldsm4t(bL, zLo + off);
            #pragma unroll
            for (int t = 0; t < 2; t++)
                #pragma unroll
                for (int s = 0; s < 2; s++) {
                    float* c = &acc[(t * 4 + p * 2 + s) * 4];
                    mma16816(c, aH[t], &bH[2 * s]);
                    mma16816(c, aH[t], &bL[2 * s]);
                    mma16816(c, aL[t], &bH[2 * s]);
                }
        }
    }
}

// ---------------- prologue kernels (tiny) ----------------
__global__ void prep_w(const float* __restrict__ W) {
    int idx = blockIdx.x * 256 + threadIdx.x;     // grid 192 -> 49152
    int l = idx >> 14, rem = idx & 16383;
    int row = rem >> 7, col = rem & 127;
    float v = W[idx];
    uint32_t b = __float_as_uint(v);
    float lo = v - __uint_as_float(b & 0xffff0000u);
    int pos = l * 16384 + row * 128 + (((col >> 3) ^ (row & 7)) << 3) + (col & 7);
    g_w_hi[pos] = (unsigned short)(b >> 16);
    g_w_lo[pos] = __bfloat16_as_ushort(__float2bfloat16(lo));
}
__global__ void prep_emb(const float* __restrict__ emb) {
    int base = (blockIdx.x * 256 + threadIdx.x) * 4;   // grid 256 -> 262144
    float4 v = *reinterpret_cast<const float4*>(emb + base);
    float vv[4] = { v.x, v.y, v.z, v.w };
    #pragma unroll
    for (int e = 0; e < 4; e++) {
        uint32_t b = __float_as_uint(vv[e]);
        float lo = vv[e] - __uint_as_float(b & 0xffff0000u);
        g_emb_hi[base + e] = (unsigned short)(b >> 16);
        g_emb_lo[base + e] = __bfloat16_as_ushort(__float2bfloat16(lo));
    }
}

// ---------------- main kernel ----------------
__global__ __launch_bounds__(256, 2)
void mpnn_main(const int* __restrict__ fps,
               const float* __restrict__ adj,
               const float* __restrict__ bias,
               float* __restrict__ out)
{
    extern __shared__ char smem[];
    const uint32_t sb = smem_u32(smem);
    const int tid = threadIdx.x, wid = tid >> 5, lane = tid & 31;
    const int bid = blockIdx.x;
    const int m_base = (wid & 1) << 5;     // 0 / 32
    const int n_base = (wid >> 1) << 5;    // 0,32,64,96

    // ---- issue emb gather (cp.async into AH, committed with W(0) below) ----
    #pragma unroll
    for (int i = 0; i < 8; i++) {
        int idx = tid + (i << 8);                  // 0..2047
        int buf = idx >> 10, rem = idx & 1023;
        int m = rem >> 4, c = rem & 15;
        int fp = fps[(bid << 6) + m];
        const unsigned short* src = (buf ? g_emb_lo : g_emb_hi) + (size_t)fp * 128 + c * 8;
        cp16(sb + SM_AH + buf * 16384 + (m << 8) + ((c ^ (m & 7)) << 4), src);
    }

    // ---- adjI = I + adj: split + swizzled STS + column-sum partials ----
    float4 s4 = make_float4(0.f, 0.f, 0.f, 0.f);
    {
        const float4* ag = reinterpret_cast<const float4*>(adj) + (size_t)bid * 1024;
        #pragma unroll
        for (int i = 0; i < 4; i++) {
            int q   = tid + (i << 8);              // float4 idx 0..1023
            int row = q >> 4;
            int c4  = (q & 15) << 2;               // constant per thread
            float4 v = ag[q];
            float a0 = v.x + ((row == c4 + 0) ? 1.0f : 0.0f);
            float a1 = v.y + ((row == c4 + 1) ? 1.0f : 0.0f);
            float a2 = v.z + ((row == c4 + 2) ? 1.0f : 0.0f);
            float a3 = v.w + ((row == c4 + 3) ? 1.0f : 0.0f);
            s4.x += a0; s4.y += a1; s4.z += a2; s4.w += a3;
            uint32_t h0, l0, h1, l1;
            pack_split(a0, a1, h0, l0);
            pack_split(a2, a3, h1, l1);
            int off = (row << 7) + ((((c4 >> 3) ^ (row & 7)) << 4) | ((c4 & 7) << 1));
            *reinterpret_cast<uint32_t*>(smem + SM_ADJ + off)        = h0;
            *reinterpret_cast<uint32_t*>(smem + SM_ADJ + off + 4)    = h1;
            *reinterpret_cast<uint32_t*>(smem + SM_ADJ_LO + off)     = l0;
            *reinterpret_cast<uint32_t*>(smem + SM_ADJ_LO + off + 4) = l1;
        }
    }
    // ---- reduce colsum partials in WZ scratch (W not staged yet) ----
    {
        float4* part = reinterpret_cast<float4*>(smem + SM_WZ);
        part[tid] = s4;
    }
    __syncthreads();
    if (tid < 16) {
        float4* part = reinterpret_cast<float4*>(smem + SM_WZ);
        float4 cs = part[tid];
        #pragma unroll
        for (int j = 1; j < 16; j++) {
            float4 p = part[tid + 16 * j];
            cs.x += p.x; cs.y += p.y; cs.z += p.z; cs.w += p.w;
        }
        *reinterpret_cast<float4*>(smem + SM_WZ + 4096 + tid * 16) = cs;
    }
    __syncthreads();

    // cache pooling weights w[m] = 1 + colsum(adj)[m] for this thread's rows
    float wreg[4];
    {
        const float* wsm = reinterpret_cast<const float*>(smem + SM_WZ + 4096);
        int mb = m_base + (lane >> 2);
        #pragma unroll
        for (int q = 0; q < 4; q++) wreg[q] = wsm[mb + 8 * q];
    }
    __syncthreads();   // all wreg reads done before W(0) staging overwrites WZ

    for (int l = 0; l < 3; l++) {
        // ---- stage W[l] ----
        #pragma unroll
        for (int i = 0; i < 16; i++) {
            int idx = tid + (i << 8);              // 0..4095
            int buf = idx >> 11, rem = idx & 2047;
            const unsigned short* src = (buf ? g_w_lo : g_w_hi) + l * 16384 + rem * 8;
            cp16(sb + SM_WZ + buf * 32768 + rem * 16, src);
        }
        CP_COMMIT();
        CP_WAIT0();
        __syncthreads();

        float acc[32];
        // ---- GEMM1: D1 = h @ W^T ----
        gemm1(acc, sb + SM_AH, sb + SM_AH_LO, sb + SM_WZ, sb + SM_WZ_LO,
              m_base, n_base, lane);
        __syncthreads();   // W reads done before z overwrites (l<2) / h reads done (l=2)

        if (l < 2) {
            // ---- epi1: z = relu(D1+b) -> z[m][k] row-major in WZ ----
            #pragma unroll
            for (int t = 0; t < 2; t++)
                #pragma unroll
                for (int nt = 0; nt < 4; nt++) {
                    float* c = &acc[(t * 4 + nt) * 4];
                    int k0 = n_base + nt * 8 + (lane & 3) * 2;
                    int m  = m_base + t * 16 + (lane >> 2);
                    float b0 = __ldg(bias + l * 128 + k0);
                    float b1 = __ldg(bias + l * 128 + k0 + 1);
                    float v0 = fmaxf(c[0] + b0, 0.0f), v1 = fmaxf(c[1] + b1, 0.0f);
                    float v2 = fmaxf(c[2] + b0, 0.0f), v3 = fmaxf(c[3] + b1, 0.0f);
                    uint32_t hi2, lo2;
                    pack_split(v0, v1, hi2, lo2);
                    int off = swz256(m, k0);
                    *reinterpret_cast<uint32_t*>(smem + SM_WZ + off)    = hi2;
                    *reinterpret_cast<uint32_t*>(smem + SM_WZ_LO + off) = lo2;
                    pack_split(v2, v3, hi2, lo2);
                    off = swz256(m + 8, k0);
                    *reinterpret_cast<uint32_t*>(smem + SM_WZ + off)    = hi2;
                    *reinterpret_cast<uint32_t*>(smem + SM_WZ_LO + off) = lo2;
                }
            __syncthreads();

            // ---- GEMM2: h' = adjI @ z ----
            gemm2(acc, sb + SM_ADJ, sb + SM_ADJ_LO, sb + SM_WZ, sb + SM_WZ_LO,
                  m_base, n_base, lane);
            #pragma unroll
            for (int t = 0; t < 2; t++)
                #pragma unroll
                for (int nt = 0; nt < 4; nt++) {
                    float* c = &acc[(t * 4 + nt) * 4];
                    int d0 = n_base + nt * 8 + (lane & 3) * 2;
                    int m  = m_base + t * 16 + (lane >> 2);
                    uint32_t hi2, lo2;
                    pack_split(c[0], c[1], hi2, lo2);
                    int off = swz256(m, d0);
                    *reinterpret_cast<uint32_t*>(smem + SM_AH + off)    = hi2;
                    *reinterpret_cast<uint32_t*>(smem + SM_AH_LO + off) = lo2;
                    pack_split(c[2], c[3], hi2, lo2);
                    off = swz256(m + 8, d0);
                    *reinterpret_cast<uint32_t*>(smem + SM_AH + off)    = hi2;
                    *reinterpret_cast<uint32_t*>(smem + SM_AH_LO + off) = lo2;
                }
            __syncthreads();
        } else {
            // ---- fused pooled epilogue: out[k] = sum_m w_m * relu(D1[m,k]+b[k]) ----
            float s[8];
            #pragma unroll
            for (int j = 0; j < 8; j++) s[j] = 0.0f;
            #pragma unroll
            for (int t = 0; t < 2; t++)
                #pragma unroll
                for (int nt = 0; nt < 4; nt++) {
                    float* c = &acc[(t * 4 + nt) * 4];
                    int k0 = n_base + nt * 8 + (lane & 3) * 2;
                    float b0 = __ldg(bias + 256 + k0);
                    float b1 = __ldg(bias + 256 + k0 + 1);
                    #pragma unroll
                    for (int r = 0; r < 4; r++) {
                        float v = fmaxf(c[r] + ((r & 1) ? b1 : b0), 0.0f);
                        s[nt * 2 + (r & 1)] += wreg[t * 2 + (r >> 1)] * v;
                    }
                }
            #pragma unroll
            for (int off = 4; off < 32; off <<= 1)
                #pragma unroll
                for (int j = 0; j < 8; j++)
                    s[j] += __shfl_xor_sync(0xffffffffu, s[j], off);

            // cross-warp combine (rows 0-31 partial + rows 32-63 partial) in ADJ scratch
            float* pool = reinterpret_cast<float*>(smem + SM_ADJ);   // ADJ dead now
            if ((wid & 1) == 0 && (lane >> 2) == 0) {
                #pragma unroll
                for (int nt = 0; nt < 4; nt++) {
                    int k = n_base + nt * 8 + (lane & 3) * 2;
                    *reinterpret_cast<float2*>(pool + k) = make_float2(s[nt * 2], s[nt * 2 + 1]);
                }
            }
            __syncthreads();
            if ((wid & 1) == 1 && (lane >> 2) == 0) {
                #pragma unroll
                for (int nt = 0; nt < 4; nt++) {
                    int k = n_base + nt * 8 + (lane & 3) * 2;
                    float2 p = *reinterpret_cast<float2*>(pool + k);
                    *reinterpret_cast<float2*>(out + (size_t)bid * 128 + k) =
                        make_float2(p.x + s[nt * 2], p.y + s[nt * 2 + 1]);
                }
            }
        }
    }
}

extern "C" void kernel_launch(void* const* d_in, const int* in_sizes, int n_in,
                              void* d_out, int out_size)
{
    (void)in_sizes; (void)n_in; (void)out_size;
    const int*   fps = (const int*)  d_in[0];
    const float* adj = (const float*)d_in[1];
    const float* emb = (const float*)d_in[2];
    const float* W   = (const float*)d_in[3];
    const float* b   = (const float*)d_in[4];
    float*       out = (float*)d_out;

    prep_w<<<192, 256>>>(W);
    prep_emb<<<256, 256>>>(emb);

    cudaFuncSetAttribute(mpnn_main, cudaFuncAttributeMaxDynamicSharedMemorySize, SM_TOTAL);
    mpnn_main<<<4096, 256, SM_TOTAL>>>(fps, adj, b, out);
}